// round 1
// baseline (speedup 1.0000x reference)
#include <cuda_runtime.h>

// HarmonicConvolutionFilter: out[b,s,f,o] = sum_{t,k,c} x_pad[b, s+t-2, f*(k+1), c] * W[t,k,c,o]
// with harmonic gather valid only when f*(k+1) < F.
// Shapes: x [B=4, S=1024, F=512, C=4] f32, W [5,4,4,4] f32, out [B,S,F,O=4] f32.

#define B_ 4
#define S_ 1024
#define F_ 512
#define NT 5   // 2T+1
#define NK 4

__global__ __launch_bounds__(256) void harm_conv_kernel(
    const float* __restrict__ x,
    const float* __restrict__ W,
    float* __restrict__ out)
{
    // Stage weights in shared: Wsm[t][k][c] = float4 over o
    __shared__ float4 Wsm[NT][NK][4];
    int tid = threadIdx.x;
    if (tid < NT * NK * 4) {
        reinterpret_cast<float4*>(Wsm)[tid] =
            reinterpret_cast<const float4*>(W)[tid];
    }
    __syncthreads();

    int gid = blockIdx.x * 256 + tid;          // gid = ((b*S + s)*F + f)
    int f = gid & (F_ - 1);
    int s = (gid >> 9) & (S_ - 1);
    int b = gid >> 19;

    const float4* __restrict__ x4 = reinterpret_cast<const float4*>(x);

    float4 acc = make_float4(0.f, 0.f, 0.f, 0.f);

#pragma unroll
    for (int t = 0; t < NT; ++t) {
        int sp = s + t - 2;                    // time tap (T=2 padding -> skip OOB)
        if (sp < 0 || sp >= S_) continue;
        const float4* __restrict__ xrow = x4 + (size_t)(b * S_ + sp) * F_;
#pragma unroll
        for (int k = 0; k < NK; ++k) {
            int fk = f * (k + 1);
            if (fk >= F_) break;               // monotone in k -> early exit
            float4 xv = xrow[fk];
            float4 w0 = Wsm[t][k][0];
            float4 w1 = Wsm[t][k][1];
            float4 w2 = Wsm[t][k][2];
            float4 w3 = Wsm[t][k][3];
            acc.x += xv.x * w0.x + xv.y * w1.x + xv.z * w2.x + xv.w * w3.x;
            acc.y += xv.x * w0.y + xv.y * w1.y + xv.z * w2.y + xv.w * w3.y;
            acc.z += xv.x * w0.z + xv.y * w1.z + xv.z * w2.z + xv.w * w3.z;
            acc.w += xv.x * w0.w + xv.y * w1.w + xv.z * w2.w + xv.w * w3.w;
        }
    }

    reinterpret_cast<float4*>(out)[gid] = acc;
}

extern "C" void kernel_launch(void* const* d_in, const int* in_sizes, int n_in,
                              void* d_out, int out_size)
{
    const float* x = (const float*)d_in[0];
    const float* W = (const float*)d_in[1];
    float* out = (float*)d_out;

    int total = B_ * S_ * F_;                  // threads, one per (b,s,f)
    harm_conv_kernel<<<total / 256, 256>>>(x, W, out);
}

// round 2
// speedup vs baseline: 1.4096x; 1.4096x over previous
#include <cuda_runtime.h>

// out[b,s,f,o] = sum_{t,k,c} x[b, s+t-2, f*(k+1), c] * W[t,k,c,o],  f*(k+1) < F
// x [4,1024,512,4] f32, W [5,4,4,4] f32, out [4,1024,512,4] f32.
//
// R2: rolling time-window (U=8 outputs/thread, 3.3x fewer gather loads) +
//     weights in __constant__ (LDCU uniform port, zero L1TEX weight traffic).

#define B_ 4
#define S_ 1024
#define F_ 512
#define U_ 8
#define NT 5
#define NK 4

__constant__ float4 Wc[NT][NK][4];   // [t][k][c] -> float4 over o

__global__ __launch_bounds__(256) void harm_conv_kernel(
    const float* __restrict__ x,
    float* __restrict__ out)
{
    int gid = blockIdx.x * 256 + threadIdx.x;
    int f  = gid & (F_ - 1);                     // fastest: coalesced k=0 gather + stores
    int sb = (gid >> 9) & (S_ / U_ - 1);
    int b  = gid >> 16;
    int s0 = sb * U_;

    const float4* __restrict__ x4 = reinterpret_cast<const float4*>(x);
    const float4* __restrict__ xb = x4 + (size_t)b * S_ * F_;

    float4 acc[U_];
#pragma unroll
    for (int j = 0; j < U_; ++j) acc[j] = make_float4(0.f, 0.f, 0.f, 0.f);

    for (int k = 0; k < NK; ++k) {
        int fk = f * (k + 1);
        if (fk >= F_) break;                     // monotone in k, warp-coherent
        const float4* __restrict__ col = xb + fk;

#pragma unroll
        for (int i = -2; i < U_ + 2; ++i) {      // rows s0-2 .. s0+U+1
            int sp = s0 + i;
            float4 xv;
            if (sp >= 0 && sp < S_)
                xv = col[(size_t)sp * F_];
            else
                xv = make_float4(0.f, 0.f, 0.f, 0.f);

#pragma unroll
            for (int t = 0; t < NT; ++t) {       // tap t feeds output j = i+2-t
                int j = i + 2 - t;
                if (j >= 0 && j < U_) {
                    float4 w0 = Wc[t][k][0];
                    float4 w1 = Wc[t][k][1];
                    float4 w2 = Wc[t][k][2];
                    float4 w3 = Wc[t][k][3];
                    acc[j].x += xv.x * w0.x + xv.y * w1.x + xv.z * w2.x + xv.w * w3.x;
                    acc[j].y += xv.x * w0.y + xv.y * w1.y + xv.z * w2.y + xv.w * w3.y;
                    acc[j].z += xv.x * w0.z + xv.y * w1.z + xv.z * w2.z + xv.w * w3.z;
                    acc[j].w += xv.x * w0.w + xv.y * w1.w + xv.z * w2.w + xv.w * w3.w;
                }
            }
        }
    }

    float4* __restrict__ o4 =
        reinterpret_cast<float4*>(out) + ((size_t)(b * S_ + s0)) * F_ + f;
#pragma unroll
    for (int j = 0; j < U_; ++j)
        o4[(size_t)j * F_] = acc[j];
}

extern "C" void kernel_launch(void* const* d_in, const int* in_sizes, int n_in,
                              void* d_out, int out_size)
{
    const float* x = (const float*)d_in[0];
    const float* W = (const float*)d_in[1];
    float* out = (float*)d_out;

    // capture-legal: async device-to-device copy into constant bank
    cudaMemcpyToSymbolAsync(Wc, W, NT * NK * 4 * 4 * sizeof(float), 0,
                            cudaMemcpyDeviceToDevice, 0);

    int total = B_ * (S_ / U_) * F_;             // one thread per (b, s-block, f)
    harm_conv_kernel<<<total / 256, 256>>>(x, out);
}

// round 3
// speedup vs baseline: 1.6009x; 1.1358x over previous
#include <cuda_runtime.h>

// out[b,s,f,o] = sum_{t,k,c} x[b, s+t-2, f*(k+1), c] * W[t,k,c,o],  f*(k+1) < F
// x [4,1024,512,4] f32, W [5,4,4,4] f32, out [4,1024,512,4] f32.
//
// R3: packed fma.rn.f32x2 (FFMA2) over the o-dimension — 8 FFMA2 per (t,k) site
//     instead of 16 FFMA. Weights live in __constant__ as packed o-pairs
//     (same bit layout as float4). Rolling time window U=8 kept from R2.

#define B_ 4
#define S_ 1024
#define F_ 512
#define U_ 8
#define NT 5
#define NK 4

typedef unsigned long long u64;

// W[t][k][c][o0..o3] as two packed f32x2 pairs: .x=(o0,o1), .y=(o2,o3)
__constant__ ulonglong2 Wc2[NT][NK][4];

__device__ __forceinline__ u64 fma2(u64 a, u64 b, u64 c) {
    u64 d;
    asm("fma.rn.f32x2 %0, %1, %2, %3;" : "=l"(d) : "l"(a), "l"(b), "l"(c));
    return d;
}
__device__ __forceinline__ u64 dup2(float v) {
    u64 d;
    asm("mov.b64 %0, {%1, %1};" : "=l"(d) : "f"(v));
    return d;
}

__global__ __launch_bounds__(256) void harm_conv_kernel(
    const float* __restrict__ x,
    float* __restrict__ out)
{
    int gid = blockIdx.x * 256 + threadIdx.x;
    int f  = gid & (F_ - 1);                    // fastest: coalesced k=0 gather + stores
    int sb = (gid >> 9) & (S_ / U_ - 1);
    int b  = gid >> 16;
    int s0 = sb * U_;

    const float4* __restrict__ xb =
        reinterpret_cast<const float4*>(x) + (size_t)b * S_ * F_;

    u64 acc[U_][2];
#pragma unroll
    for (int j = 0; j < U_; ++j) { acc[j][0] = 0ull; acc[j][1] = 0ull; }

    for (int k = 0; k < NK; ++k) {
        int fk = f * (k + 1);
        if (fk >= F_) break;                    // monotone in k, warp-coherent
        const float4* __restrict__ col = xb + fk;

#pragma unroll
        for (int i = -2; i < U_ + 2; ++i) {     // rows s0-2 .. s0+U+1
            int sp = s0 + i;
            float4 xv = (sp >= 0 && sp < S_) ? col[(size_t)sp * F_]
                                             : make_float4(0.f, 0.f, 0.f, 0.f);
            u64 dx0 = dup2(xv.x);
            u64 dx1 = dup2(xv.y);
            u64 dx2 = dup2(xv.z);
            u64 dx3 = dup2(xv.w);

#pragma unroll
            for (int t = 0; t < NT; ++t) {      // tap t feeds output j = i+2-t
                int j = i + 2 - t;
                if (j >= 0 && j < U_) {
                    ulonglong2 w0 = Wc2[t][k][0];
                    ulonglong2 w1 = Wc2[t][k][1];
                    ulonglong2 w2 = Wc2[t][k][2];
                    ulonglong2 w3 = Wc2[t][k][3];
                    acc[j][0] = fma2(dx0, w0.x, acc[j][0]);
                    acc[j][1] = fma2(dx0, w0.y, acc[j][1]);
                    acc[j][0] = fma2(dx1, w1.x, acc[j][0]);
                    acc[j][1] = fma2(dx1, w1.y, acc[j][1]);
                    acc[j][0] = fma2(dx2, w2.x, acc[j][0]);
                    acc[j][1] = fma2(dx2, w2.y, acc[j][1]);
                    acc[j][0] = fma2(dx3, w3.x, acc[j][0]);
                    acc[j][1] = fma2(dx3, w3.y, acc[j][1]);
                }
            }
        }
    }

    // store: reinterpret packed pairs as float4
    float4* __restrict__ o4 =
        reinterpret_cast<float4*>(out) + ((size_t)(b * S_ + s0)) * F_ + f;
#pragma unroll
    for (int j = 0; j < U_; ++j) {
        float2 lo = *reinterpret_cast<float2*>(&acc[j][0]);
        float2 hi = *reinterpret_cast<float2*>(&acc[j][1]);
        o4[(size_t)j * F_] = make_float4(lo.x, lo.y, hi.x, hi.y);
    }
}

extern "C" void kernel_launch(void* const* d_in, const int* in_sizes, int n_in,
                              void* d_out, int out_size)
{
    const float* x = (const float*)d_in[0];
    const float* W = (const float*)d_in[1];
    float* out = (float*)d_out;

    cudaMemcpyToSymbolAsync(Wc2, W, NT * NK * 4 * 4 * sizeof(float), 0,
                            cudaMemcpyDeviceToDevice, 0);

    int total = B_ * (S_ / U_) * F_;            // one thread per (b, s-block, f)
    harm_conv_kernel<<<total / 256, 256>>>(x, out);
}

// round 4
// speedup vs baseline: 1.7633x; 1.1014x over previous
#include <cuda_runtime.h>

// out[b,s,f,o] = sum_{t,k,c} x[b, s+t-2, f*(k+1), c] * W[t,k,c,o],  f*(k+1) < F
// x [4,1024,512,4] f32, W [5,4,4,4] f32, out [4,1024,512,4] f32.
//
// R4: FFMA2 packed over the CHANNEL dim (gathered float4 is already two f32x2
//     pairs -> zero dup movs), weights transposed to [k][t][o][c] in smem,
//     t-inner structure bounds weight liveness to 16 regs, U=4, 128-thr blocks.

#define B_  4
#define S_  1024
#define F_  512
#define U_  4
#define NT  5
#define NK  4
#define TPB 128

typedef unsigned long long u64;

__device__ __forceinline__ u64 fma2(u64 a, u64 b, u64 c) {
    u64 d;
    asm("fma.rn.f32x2 %0, %1, %2, %3;" : "=l"(d) : "l"(a), "l"(b), "l"(c));
    return d;
}

__global__ __launch_bounds__(TPB) void harm_conv_kernel(
    const float* __restrict__ x,
    const float* __restrict__ W,
    float* __restrict__ out)
{
    // Ws2[(k*NT+t)*4 + o] = floats (c0,c1,c2,c3): .x=(c0,c1) .y=(c2,c3)
    __shared__ ulonglong2 Ws2[NK * NT * 4];
    int tid = threadIdx.x;
    {
        float* wsf = reinterpret_cast<float*>(Ws2);
        for (int i = tid; i < NT * NK * 4 * 4; i += TPB) {
            // src linear: ((t*NK + k)*4 + c)*4 + o
            int o = i & 3, c = (i >> 2) & 3, k = (i >> 4) & 3, t = i >> 6;
            wsf[((k * NT + t) * 4 + o) * 4 + c] = W[i];
        }
    }
    __syncthreads();

    int gid = blockIdx.x * TPB + tid;
    int f  = gid & (F_ - 1);                    // fastest: coalesced k=0 gather + stores
    int sb = (gid >> 9) & (S_ / U_ - 1);
    int b  = gid >> 17;
    int s0 = sb * U_;

    const ulonglong2* __restrict__ xb =
        reinterpret_cast<const ulonglong2*>(x) + (size_t)b * S_ * F_;

    u64 acc[U_][4];                             // [j][o], each packed over c-pairs
#pragma unroll
    for (int j = 0; j < U_; ++j)
#pragma unroll
        for (int o = 0; o < 4; ++o) acc[j][o] = 0ull;

    for (int k = 0; k < NK; ++k) {
        int fk = f * (k + 1);
        if (fk >= F_) break;                    // monotone in k, warp-coherent
        const ulonglong2* __restrict__ col = xb + fk;

        ulonglong2 row[U_ + 4];                 // sp = s0-2 .. s0+U+1
#pragma unroll
        for (int i = 0; i < U_ + 4; ++i) {
            int sp = s0 + i - 2;
            if (sp >= 0 && sp < S_) row[i] = col[(size_t)sp * F_];
            else                    row[i] = make_ulonglong2(0ull, 0ull);
        }

#pragma unroll
        for (int t = 0; t < NT; ++t) {
            const ulonglong2* wp = &Ws2[(k * NT + t) * 4];
            ulonglong2 w0 = wp[0], w1 = wp[1], w2 = wp[2], w3 = wp[3];
#pragma unroll
            for (int j = 0; j < U_; ++j) {
                ulonglong2 r = row[j + t];
                acc[j][0] = fma2(r.x, w0.x, acc[j][0]);
                acc[j][1] = fma2(r.x, w1.x, acc[j][1]);
                acc[j][2] = fma2(r.x, w2.x, acc[j][2]);
                acc[j][3] = fma2(r.x, w3.x, acc[j][3]);
                acc[j][0] = fma2(r.y, w0.y, acc[j][0]);
                acc[j][1] = fma2(r.y, w1.y, acc[j][1]);
                acc[j][2] = fma2(r.y, w2.y, acc[j][2]);
                acc[j][3] = fma2(r.y, w3.y, acc[j][3]);
            }
        }
    }

    // epilogue: horizontal add of the two c-halves per output
    float4* __restrict__ o4 =
        reinterpret_cast<float4*>(out) + ((size_t)(b * S_ + s0)) * F_ + f;
#pragma unroll
    for (int j = 0; j < U_; ++j) {
        float2 a0 = reinterpret_cast<float2&>(acc[j][0]);
        float2 a1 = reinterpret_cast<float2&>(acc[j][1]);
        float2 a2 = reinterpret_cast<float2&>(acc[j][2]);
        float2 a3 = reinterpret_cast<float2&>(acc[j][3]);
        o4[(size_t)j * F_] = make_float4(a0.x + a0.y, a1.x + a1.y,
                                         a2.x + a2.y, a3.x + a3.y);
    }
}

extern "C" void kernel_launch(void* const* d_in, const int* in_sizes, int n_in,
                              void* d_out, int out_size)
{
    const float* x = (const float*)d_in[0];
    const float* W = (const float*)d_in[1];
    float* out = (float*)d_out;

    int total = B_ * (S_ / U_) * F_;            // one thread per (b, s-block, f)
    harm_conv_kernel<<<total / TPB, TPB>>>(x, W, out);
}